// round 4
// baseline (speedup 1.0000x reference)
#include <cuda_runtime.h>

#define HID 256
#define PPB 4          // points per block (packed as 2 f32x2 pairs)
#define NPT 4          // neurons per thread
#define TPB 64         // TPB * NPT == HID

typedef unsigned long long ull;

// packed fp32x2 fma: acc = a * b + acc  (exact fp32, Blackwell FFMA2)
#define FMA2(acc, a, b) asm("fma.rn.f32x2 %0, %1, %2, %0;" : "+l"(acc) : "l"(a), "l"(b))
// duplicate one fp32 into both lanes of an f32x2
#define DUP2(d, s) asm("mov.b64 %0, {%1, %1};" : "=l"(d) : "r"(__float_as_uint(s)))

__device__ __forceinline__ float2 u2f2(ull u) {
    float2 f;
    f.x = __uint_as_float((unsigned)(u & 0xffffffffu));
    f.y = __uint_as_float((unsigned)(u >> 32));
    return f;
}

__device__ __forceinline__ void swish_derivs(float z, float& s, float& sp, float& spp) {
    float sig = 1.0f / (1.0f + __expf(-z));
    float om  = 1.0f - sig;
    s   = z * sig;
    sp  = sig * (1.0f + z * om);
    spp = sig * om * (2.0f + z * (1.0f - 2.0f * sig));
}

__global__ __launch_bounds__(TPB)
void pinn_burgers2d_kernel(
    const float* __restrict__ x, const float* __restrict__ y,
    const float* __restrict__ t, const float* __restrict__ nu,
    const float* __restrict__ W0, const float* __restrict__ b0,
    const float* __restrict__ W1, const float* __restrict__ b1,
    const float* __restrict__ W2, const float* __restrict__ b2,
    const float* __restrict__ W3, const float* __restrict__ b3,
    const float* __restrict__ W4, const float* __restrict__ b4,
    float* __restrict__ out, int N)
{
    // state: [channel][neuron][point]  (point innermost -> f32x2-packable)
    // channels: 0=h,1=hx,2=hy,3=ht,4=hxx,5=hyy
    __shared__ float S[6][HID][PPB];   // 24 KB

    const int tid  = threadIdx.x;       // 0..63
    const int n0   = NPT * tid;         // this thread owns neurons n0..n0+3
    const int base = blockIdx.x * PPB;

    // ---------------- layer 0: (4 -> 256) + swish ----------------
    {
        const float4 w0 = *reinterpret_cast<const float4*>(&W0[0 * HID + n0]);
        const float4 w1 = *reinterpret_cast<const float4*>(&W0[1 * HID + n0]);
        const float4 w2 = *reinterpret_cast<const float4*>(&W0[2 * HID + n0]);
        const float4 w3 = *reinterpret_cast<const float4*>(&W0[3 * HID + n0]);
        const float4 bb = *reinterpret_cast<const float4*>(&b0[n0]);
        const float* w0a = &w0.x; const float* w1a = &w1.x;
        const float* w2a = &w2.x; const float* w3a = &w3.x;
        const float* bba = &bb.x;

        float o[6][NPT][PPB];
        #pragma unroll
        for (int p = 0; p < PPB; p++) {
            int idx = base + p; if (idx >= N) idx = N - 1;
            const float xs = x[idx];
            const float ys = y[idx];
            const float ts = 2.0f * t[idx] - 1.0f;
            const float ns = 2.0f * (nu[idx] - 0.01f) * (1.0f / 0.09f) - 1.0f;
            #pragma unroll
            for (int q = 0; q < NPT; q++) {
                const float z  = fmaf(xs, w0a[q], fmaf(ys, w1a[q], fmaf(ts, w2a[q], fmaf(ns, w3a[q], bba[q]))));
                const float zx = w0a[q], zy = w1a[q], zt = 2.0f * w2a[q];
                float s, sp, spp; swish_derivs(z, s, sp, spp);
                o[0][q][p] = s;
                o[1][q][p] = sp * zx;
                o[2][q][p] = sp * zy;
                o[3][q][p] = sp * zt;
                o[4][q][p] = spp * zx * zx;
                o[5][q][p] = spp * zy * zy;
            }
        }
        #pragma unroll
        for (int s = 0; s < 6; s++)
            #pragma unroll
            for (int q = 0; q < NPT; q++)
                *reinterpret_cast<float4*>(&S[s][n0 + q][0]) =
                    make_float4(o[s][q][0], o[s][q][1], o[s][q][2], o[s][q][3]);
    }
    __syncthreads();

    // ---------------- hidden layers 1..3: (256 -> 256) + swish ----------------
    #pragma unroll 1
    for (int l = 0; l < 3; l++) {
        const float* __restrict__ W = (l == 0) ? W1 : (l == 1) ? W2 : W3;
        const float* __restrict__ b = (l == 0) ? b1 : (l == 1) ? b2 : b3;

        // acc[s][q][pair]: packed f32x2 over point pairs (0,1) and (2,3)
        ull acc[6][NPT][2];
        #pragma unroll
        for (int s = 0; s < 6; s++)
            #pragma unroll
            for (int q = 0; q < NPT; q++) { acc[s][q][0] = 0ull; acc[s][q][1] = 0ull; }

        #pragma unroll 1
        for (int k = 0; k < HID; k += 4) {
            const float4 wa = *reinterpret_cast<const float4*>(&W[(k + 0) * HID + n0]);
            const float4 wb = *reinterpret_cast<const float4*>(&W[(k + 1) * HID + n0]);
            const float4 wc = *reinterpret_cast<const float4*>(&W[(k + 2) * HID + n0]);
            const float4 wd = *reinterpret_cast<const float4*>(&W[(k + 3) * HID + n0]);

            #pragma unroll
            for (int ks = 0; ks < 4; ks++) {
                const float4& wr = (ks == 0) ? wa : (ks == 1) ? wb : (ks == 2) ? wc : wd;
                ull wd2[NPT];
                DUP2(wd2[0], wr.x);
                DUP2(wd2[1], wr.y);
                DUP2(wd2[2], wr.z);
                DUP2(wd2[3], wr.w);
                #pragma unroll
                for (int s = 0; s < 6; s++) {
                    const ulonglong2 v = *reinterpret_cast<const ulonglong2*>(&S[s][k + ks][0]);
                    #pragma unroll
                    for (int q = 0; q < NPT; q++) {
                        FMA2(acc[s][q][0], wd2[q], v.x);
                        FMA2(acc[s][q][1], wd2[q], v.y);
                    }
                }
            }
        }
        const float4 bb = *reinterpret_cast<const float4*>(&b[n0]);
        const float* bba = &bb.x;
        __syncthreads();   // all reads of S done before anyone overwrites

        #pragma unroll
        for (int q = 0; q < NPT; q++) {
            // unpack accumulators for this neuron: [channel][point]
            float az[6][PPB];
            #pragma unroll
            for (int s = 0; s < 6; s++) {
                const float2 lo = u2f2(acc[s][q][0]);
                const float2 hi = u2f2(acc[s][q][1]);
                az[s][0] = lo.x; az[s][1] = lo.y; az[s][2] = hi.x; az[s][3] = hi.y;
            }
            float o[6][PPB];
            #pragma unroll
            for (int p = 0; p < PPB; p++) {
                float s, sp, spp;
                swish_derivs(az[0][p] + bba[q], s, sp, spp);
                o[0][p] = s;
                o[1][p] = sp * az[1][p];
                o[2][p] = sp * az[2][p];
                o[3][p] = sp * az[3][p];
                o[4][p] = fmaf(spp, az[1][p] * az[1][p], sp * az[4][p]);
                o[5][p] = fmaf(spp, az[2][p] * az[2][p], sp * az[5][p]);
            }
            #pragma unroll
            for (int s = 0; s < 6; s++)
                *reinterpret_cast<float4*>(&S[s][n0 + q][0]) =
                    make_float4(o[s][0], o[s][1], o[s][2], o[s][3]);
        }
        __syncthreads();
    }

    // ---------------- final layer (256 -> 2) + PDE residual ----------------
    // 2 warps; warp w handles points w and w+2; lanes stride over k.
    const int warp = tid >> 5;      // 0..1
    const int lane = tid & 31;

    #pragma unroll
    for (int pp = 0; pp < 2; pp++) {
        const int p = warp + 2 * pp;

        float a[12];  // a[2*s+o]: s in {h,x,y,t,xx,yy}, o in {u,v}
        #pragma unroll
        for (int r = 0; r < 12; r++) a[r] = 0.0f;

        #pragma unroll
        for (int i = 0; i < HID / 32; i++) {
            const int k = lane + 32 * i;
            const float2 w = *reinterpret_cast<const float2*>(&W4[2 * k]);
            #pragma unroll
            for (int s = 0; s < 6; s++) {
                const float v = S[s][k][p];
                a[2 * s + 0] = fmaf(v, w.x, a[2 * s + 0]);
                a[2 * s + 1] = fmaf(v, w.y, a[2 * s + 1]);
            }
        }
        #pragma unroll
        for (int r = 0; r < 12; r++) {
            #pragma unroll
            for (int off = 16; off > 0; off >>= 1)
                a[r] += __shfl_xor_sync(0xffffffffu, a[r], off);
        }

        if (lane == 0) {
            const int idx = base + p;
            if (idx < N) {
                const float u   = a[0] + b4[0];
                const float v   = a[1] + b4[1];
                const float u_x = a[2],  v_x = a[3];
                const float u_y = a[4],  v_y = a[5];
                const float u_t = a[6],  v_t = a[7];
                const float u_xx = a[8], v_xx = a[9];
                const float u_yy = a[10], v_yy = a[11];
                const float nv = nu[idx];
                const float fu = u_t + u * u_x + v * u_y - nv * (u_xx + u_yy);
                const float fv = v_t + u * v_x + v * v_y - nv * (v_xx + v_yy);
                out[2 * idx + 0] = fu;
                out[2 * idx + 1] = fv;
            }
        }
    }
}

extern "C" void kernel_launch(void* const* d_in, const int* in_sizes, int n_in,
                              void* d_out, int out_size) {
    const float* x  = (const float*)d_in[0];
    const float* y  = (const float*)d_in[1];
    const float* t  = (const float*)d_in[2];
    const float* nu = (const float*)d_in[3];
    const float* W0 = (const float*)d_in[4];
    const float* b0 = (const float*)d_in[5];
    const float* W1 = (const float*)d_in[6];
    const float* b1 = (const float*)d_in[7];
    const float* W2 = (const float*)d_in[8];
    const float* b2 = (const float*)d_in[9];
    const float* W3 = (const float*)d_in[10];
    const float* b3 = (const float*)d_in[11];
    const float* W4 = (const float*)d_in[12];
    const float* b4 = (const float*)d_in[13];
    float* out = (float*)d_out;

    const int N = in_sizes[0];
    const int blocks = (N + PPB - 1) / PPB;

    pinn_burgers2d_kernel<<<blocks, TPB>>>(x, y, t, nu,
                                           W0, b0, W1, b1, W2, b2, W3, b3, W4, b4,
                                           out, N);
}

// round 7
// speedup vs baseline: 1.2827x; 1.2827x over previous
#include <cuda_runtime.h>
#include <cuda_bf16.h>
#include <cstdint>

#define NPTS 16           // points per CTA
#define MROWS 96          // 16 points x 6 channels
#define TPB 256

// ---- SMEM layout (byte offsets from 1024-aligned base) ----
#define ASTR    528       // A row stride bytes (264 halves; 256 used + pad) -> conflict-free ldmatrix
#define OFF_AHI 0         // 96*528 = 50688
#define OFF_ALO 50688     // ends 101376
#define OFF_B   101376    // B stage: 2 splits x (64 rows x 528 B) = 67584 (ends 168960)
#define BSPL    33792
#define BSTR    528
#define OFF_SCR 101376    // fp32 scratch [96][260] = 99840 — ALIASES B (temporally disjoint)
#define SCRSTR  260
#define SMEM_BYTES (201216 + 1024)

// pre-split weights (hi/lo bf16), [3 layers][256 k][256 n]
__device__ __align__(16) __nv_bfloat16 g_Whi[3 * 256 * 256];
__device__ __align__(16) __nv_bfloat16 g_Wlo[3 * 256 * 256];

#define LDSM4(R0,R1,R2,R3,ADDR) \
  asm volatile("ldmatrix.sync.aligned.m8n8.x4.shared.b16 {%0,%1,%2,%3}, [%4];" \
    : "=r"(R0),"=r"(R1),"=r"(R2),"=r"(R3) : "r"(ADDR))
#define LDSM4T(R0,R1,R2,R3,ADDR) \
  asm volatile("ldmatrix.sync.aligned.m8n8.x4.trans.shared.b16 {%0,%1,%2,%3}, [%4];" \
    : "=r"(R0),"=r"(R1),"=r"(R2),"=r"(R3) : "r"(ADDR))
#define MMA_BF16(D,A0,A1,A2,A3,B0,B1) \
  asm volatile("mma.sync.aligned.m16n8k16.row.col.f32.bf16.bf16.f32 " \
    "{%0,%1,%2,%3},{%4,%5,%6,%7},{%8,%9},{%0,%1,%2,%3};" \
    : "+f"(D[0]),"+f"(D[1]),"+f"(D[2]),"+f"(D[3]) \
    : "r"(A0),"r"(A1),"r"(A2),"r"(A3),"r"(B0),"r"(B1))

__device__ __forceinline__ uint32_t smem_u32(const void* p) {
    uint32_t a;
    asm("{ .reg .u64 t; cvta.to.shared.u64 t, %1; cvt.u32.u64 %0, t; }" : "=r"(a) : "l"(p));
    return a;
}

__device__ __forceinline__ void swish_derivs(float z, float& s, float& sp, float& spp) {
    float sig = 1.0f / (1.0f + __expf(-z));
    float om  = 1.0f - sig;
    s   = z * sig;
    sp  = sig * (1.0f + z * om);
    spp = sig * om * (2.0f + z * (1.0f - 2.0f * sig));
}

// write value as bf16 hi/lo into A buffers; row-major, 528B row stride
__device__ __forceinline__ void storeA(char* sm, int row, int k, float v) {
    const uint32_t o = (uint32_t)row * ASTR + (uint32_t)k * 2;
    __nv_bfloat16 hi = __float2bfloat16(v);
    float rem = v - __bfloat162float(hi);
    __nv_bfloat16 lo = __float2bfloat16(rem);
    *reinterpret_cast<__nv_bfloat16*>(sm + OFF_AHI + o) = hi;
    *reinterpret_cast<__nv_bfloat16*>(sm + OFF_ALO + o) = lo;
}

// ---- prep: split W1..W3 into bf16 hi/lo ----
__global__ void prep_kernel(const float* __restrict__ W1, const float* __restrict__ W2,
                            const float* __restrict__ W3) {
    int i = blockIdx.x * blockDim.x + threadIdx.x;
    if (i >= 3 * 65536) return;
    const int layer = i >> 16;
    const int r = i & 65535;
    const float* W = (layer == 0) ? W1 : (layer == 1) ? W2 : W3;
    const float w = W[r];
    __nv_bfloat16 hi = __float2bfloat16(w);
    float rem = w - __bfloat162float(hi);
    g_Whi[i] = hi;
    g_Wlo[i] = __float2bfloat16(rem);
}

// ---- main kernel ----
__global__ __launch_bounds__(TPB, 1)
void pinn_mma_kernel(
    const float* __restrict__ x, const float* __restrict__ y,
    const float* __restrict__ t, const float* __restrict__ nu,
    const float* __restrict__ W0, const float* __restrict__ b0,
    const float* __restrict__ b1, const float* __restrict__ b2,
    const float* __restrict__ b3,
    const float* __restrict__ W4, const float* __restrict__ b4,
    float* __restrict__ out, int N)
{
    extern __shared__ char smem_raw[];
    const uint32_t rawa = smem_u32(smem_raw);
    const uint32_t sbase = (rawa + 1023u) & ~1023u;
    char* sm = smem_raw + (sbase - rawa);
    float* scr = reinterpret_cast<float*>(sm + OFF_SCR);   // [96][260], aliases B stage

    const int tid  = threadIdx.x;
    const int wid  = tid >> 5;
    const int lane = tid & 31;
    const int base = blockIdx.x * NPTS;

    const int mg = wid >> 2;          // 0..1 : M group (rows mg*48 .. +47)
    const int n0 = (wid & 3) * 64;    // N group start

    // ---------------- layer 0: (4 -> 256) scalar -> A hi/lo -----------------
    {
        const int n = tid;
        const float w0 = W0[n], w1 = W0[256 + n], w2 = W0[512 + n], w3 = W0[768 + n];
        const float bb = b0[n];
        #pragma unroll 1
        for (int p = 0; p < NPTS; p++) {
            int idx = base + p; if (idx >= N) idx = N - 1;
            const float xs = x[idx];
            const float ys = y[idx];
            const float ts = 2.0f * t[idx] - 1.0f;
            const float ns = 2.0f * (nu[idx] - 0.01f) * (1.0f / 0.09f) - 1.0f;
            const float z  = fmaf(xs, w0, fmaf(ys, w1, fmaf(ts, w2, fmaf(ns, w3, bb))));
            const float zx = w0, zy = w1, zt = 2.0f * w2;
            float s, sp, spp; swish_derivs(z, s, sp, spp);
            const int rb = p * 6;
            storeA(sm, rb + 0, n, s);
            storeA(sm, rb + 1, n, sp * zx);
            storeA(sm, rb + 2, n, sp * zy);
            storeA(sm, rb + 3, n, sp * zt);
            storeA(sm, rb + 4, n, spp * zx * zx);
            storeA(sm, rb + 5, n, spp * zy * zy);
        }
    }

    // ---------------- 3 hidden layers: bf16-split GEMM + swish --------------
    #pragma unroll 1
    for (int L = 0; L < 3; L++) {
        const float* __restrict__ bptr = (L == 0) ? b1 : (L == 1) ? b2 : b3;

        float acc[3][8][4];
        #pragma unroll
        for (int m = 0; m < 3; m++)
            #pragma unroll
            for (int nt = 0; nt < 8; nt++)
                #pragma unroll
                for (int r = 0; r < 4; r++) acc[m][nt][r] = 0.0f;

        #pragma unroll 1
        for (int kc = 0; kc < 4; kc++) {
            // stage W chunk (hi,lo): [64 k][256 n] bf16 -> smem rows of 528B
            __syncthreads();  // prior scr/B users done before overwrite
            #pragma unroll 1
            for (int i = tid; i < 4096; i += TPB) {
                const int split = i >> 11;
                const int r = (i >> 5) & 63;
                const int c = i & 31;
                const char* g = split ? (const char*)g_Wlo : (const char*)g_Whi;
                const uint4 v = *reinterpret_cast<const uint4*>(
                    g + (size_t)L * 131072 + (size_t)((kc * 64 + r) * 256 + c * 8) * 2);
                *reinterpret_cast<uint4*>(sm + OFF_B + split * BSPL + r * BSTR + c * 16) = v;
            }
            __syncthreads();

            #pragma unroll 1
            for (int split = 0; split < 3; split++) {
                // products: Ahi*Whi, Alo*Whi, Ahi*Wlo
                const uint32_t abase = sbase + ((split == 1) ? OFF_ALO : OFF_AHI);
                const uint32_t bbase = sbase + OFF_B + ((split == 2) ? BSPL : 0);
                #pragma unroll
                for (int ks = 0; ks < 4; ks++) {
                    uint32_t B[16];
                    #pragma unroll
                    for (int q = 0; q < 4; q++) {
                        const uint32_t addr = bbase
                            + (uint32_t)(ks * 16 + (lane & 15)) * BSTR
                            + (uint32_t)(n0 + q * 16 + (lane >> 4) * 8) * 2;
                        LDSM4T(B[q * 4], B[q * 4 + 1], B[q * 4 + 2], B[q * 4 + 3], addr);
                    }
                    #pragma unroll
                    for (int m = 0; m < 3; m++) {
                        uint32_t a0, a1, a2, a3;
                        const uint32_t addr = abase
                            + (uint32_t)(mg * 48 + m * 16 + (lane & 15)) * ASTR
                            + (uint32_t)(kc * 64 + ks * 16 + (lane >> 4) * 8) * 2;
                        LDSM4(a0, a1, a2, a3, addr);
                        #pragma unroll
                        for (int nt = 0; nt < 8; nt++) {
                            MMA_BF16(acc[m][nt], a0, a1, a2, a3,
                                     B[(nt >> 1) * 4 + (nt & 1) * 2],
                                     B[(nt >> 1) * 4 + (nt & 1) * 2 + 1]);
                        }
                    }
                }
            }
        }
        __syncthreads();   // B stage reads done; scr (aliased) may now be written

        // ---- epilogue: accums -> scratch -> swish chain -> A hi/lo ----
        #pragma unroll
        for (int m = 0; m < 3; m++) {
            const int row = mg * 48 + m * 16 + (lane >> 2);
            #pragma unroll
            for (int nt = 0; nt < 8; nt++) {
                const int col = n0 + nt * 8 + (lane & 3) * 2;
                float* p0 = scr + row * SCRSTR + col;
                p0[0] = acc[m][nt][0];
                p0[1] = acc[m][nt][1];
                float* p1 = p0 + 8 * SCRSTR;
                p1[0] = acc[m][nt][2];
                p1[1] = acc[m][nt][3];
            }
        }
        __syncthreads();

        {
            const int n = tid;
            const float bn = bptr[n];
            #pragma unroll 1
            for (int p = 0; p < NPTS; p++) {
                const float* zr = scr + (p * 6) * SCRSTR + n;
                const float z   = zr[0] + bn;
                const float zx  = zr[1 * SCRSTR];
                const float zy  = zr[2 * SCRSTR];
                const float zt  = zr[3 * SCRSTR];
                const float zxx = zr[4 * SCRSTR];
                const float zyy = zr[5 * SCRSTR];
                float s, sp, spp; swish_derivs(z, s, sp, spp);
                const int rb = p * 6;
                storeA(sm, rb + 0, n, s);
                storeA(sm, rb + 1, n, sp * zx);
                storeA(sm, rb + 2, n, sp * zy);
                storeA(sm, rb + 3, n, sp * zt);
                storeA(sm, rb + 4, n, fmaf(spp, zx * zx, sp * zxx));
                storeA(sm, rb + 5, n, fmaf(spp, zy * zy, sp * zyy));
            }
        }
        __syncthreads();
    }

    // ---------------- final layer (256 -> 2) + residual ---------------------
    if (tid < MROWS) {
        const int row = tid;
        float au = 0.0f, av = 0.0f;
        #pragma unroll 1
        for (int i = 0; i < 32; i++) {
            const int k0 = i * 8;
            const uint32_t o = (uint32_t)row * ASTR + (uint32_t)k0 * 2;
            const uint4 vh = *reinterpret_cast<const uint4*>(sm + OFF_AHI + o);
            const uint4 vl = *reinterpret_cast<const uint4*>(sm + OFF_ALO + o);
            const __nv_bfloat16* ph = reinterpret_cast<const __nv_bfloat16*>(&vh);
            const __nv_bfloat16* pl = reinterpret_cast<const __nv_bfloat16*>(&vl);
            #pragma unroll
            for (int e = 0; e < 8; e++) {
                const float v = __bfloat162float(ph[e]) + __bfloat162float(pl[e]);
                const float2 w = *reinterpret_cast<const float2*>(&W4[2 * (k0 + e)]);
                au = fmaf(v, w.x, au);
                av = fmaf(v, w.y, av);
            }
        }
        scr[row * 2 + 0] = au;
        scr[row * 2 + 1] = av;
    }
    __syncthreads();

    if (tid < NPTS) {
        const int idx = base + tid;
        if (idx < N) {
            const int rb = tid * 6;
            const float u   = scr[(rb + 0) * 2 + 0] + b4[0];
            const float v   = scr[(rb + 0) * 2 + 1] + b4[1];
            const float u_x = scr[(rb + 1) * 2 + 0], v_x = scr[(rb + 1) * 2 + 1];
            const float u_y = scr[(rb + 2) * 2 + 0], v_y = scr[(rb + 2) * 2 + 1];
            const float u_t = scr[(rb + 3) * 2 + 0], v_t = scr[(rb + 3) * 2 + 1];
            const float uxx = scr[(rb + 4) * 2 + 0], vxx = scr[(rb + 4) * 2 + 1];
            const float uyy = scr[(rb + 5) * 2 + 0], vyy = scr[(rb + 5) * 2 + 1];
            const float nv = nu[idx];
            out[idx * 2 + 0] = u_t + u * u_x + v * u_y - nv * (uxx + uyy);
            out[idx * 2 + 1] = v_t + u * v_x + v * v_y - nv * (vxx + vyy);
        }
    }
}

extern "C" void kernel_launch(void* const* d_in, const int* in_sizes, int n_in,
                              void* d_out, int out_size) {
    const float* x  = (const float*)d_in[0];
    const float* y  = (const float*)d_in[1];
    const float* t  = (const float*)d_in[2];
    const float* nu = (const float*)d_in[3];
    const float* W0 = (const float*)d_in[4];
    const float* b0 = (const float*)d_in[5];
    const float* W1 = (const float*)d_in[6];
    const float* b1 = (const float*)d_in[7];
    const float* W2 = (const float*)d_in[8];
    const float* b2 = (const float*)d_in[9];
    const float* W3 = (const float*)d_in[10];
    const float* b3 = (const float*)d_in[11];
    const float* W4 = (const float*)d_in[12];
    const float* b4 = (const float*)d_in[13];
    float* out = (float*)d_out;

    const int N = in_sizes[0];

    cudaFuncSetAttribute(pinn_mma_kernel, cudaFuncAttributeMaxDynamicSharedMemorySize, SMEM_BYTES);

    prep_kernel<<<(3 * 65536 + 255) / 256, 256>>>(W1, W2, W3);

    const int blocks = (N + NPTS - 1) / NPTS;
    pinn_mma_kernel<<<blocks, TPB, SMEM_BYTES>>>(x, y, t, nu, W0, b0,
                                                 b1, b2, b3, W4, b4, out, N);
}

// round 8
// speedup vs baseline: 1.6385x; 1.2774x over previous
#include <cuda_runtime.h>
#include <cuda_bf16.h>
#include <cstdint>

#define NPTS 16           // points per CTA
#define MROWS 96          // 16 points x 6 channels
#define TPB 512           // 16 warps

// ---- SMEM layout (byte offsets from 1024-aligned base) ----
#define ASTR    528       // A row stride bytes (264 halves; 256 used + pad)
#define OFF_AHI 0         // 96*528 = 50688
#define OFF_ALO 50688     // ends 101376
#define OFF_B   101376    // B stage: 2 splits x (64 rows x 528 B) = 67584
#define BSPL    33792
#define BSTR    528
#define OFF_SCR 101376    // fp32 scratch [96][260] = 99840 — ALIASES B (temporally disjoint)
#define SCRSTR  260
#define SMEM_BYTES (201216 + 1024)

// pre-split weights (hi/lo bf16), [3 layers][256 k][256 n]
__device__ __align__(16) __nv_bfloat16 g_Whi[3 * 256 * 256];
__device__ __align__(16) __nv_bfloat16 g_Wlo[3 * 256 * 256];

#define LDSM4(R0,R1,R2,R3,ADDR) \
  asm volatile("ldmatrix.sync.aligned.m8n8.x4.shared.b16 {%0,%1,%2,%3}, [%4];" \
    : "=r"(R0),"=r"(R1),"=r"(R2),"=r"(R3) : "r"(ADDR))
#define LDSM4T(R0,R1,R2,R3,ADDR) \
  asm volatile("ldmatrix.sync.aligned.m8n8.x4.trans.shared.b16 {%0,%1,%2,%3}, [%4];" \
    : "=r"(R0),"=r"(R1),"=r"(R2),"=r"(R3) : "r"(ADDR))
#define MMA_BF16(D,A0,A1,A2,A3,B0,B1) \
  asm volatile("mma.sync.aligned.m16n8k16.row.col.f32.bf16.bf16.f32 " \
    "{%0,%1,%2,%3},{%4,%5,%6,%7},{%8,%9},{%0,%1,%2,%3};" \
    : "+f"(D[0]),"+f"(D[1]),"+f"(D[2]),"+f"(D[3]) \
    : "r"(A0),"r"(A1),"r"(A2),"r"(A3),"r"(B0),"r"(B1))

__device__ __forceinline__ uint32_t smem_u32(const void* p) {
    uint32_t a;
    asm("{ .reg .u64 t; cvta.to.shared.u64 t, %1; cvt.u32.u64 %0, t; }" : "=r"(a) : "l"(p));
    return a;
}

__device__ __forceinline__ void swish_derivs(float z, float& s, float& sp, float& spp) {
    float sig = 1.0f / (1.0f + __expf(-z));
    float om  = 1.0f - sig;
    s   = z * sig;
    sp  = sig * (1.0f + z * om);
    spp = sig * om * (2.0f + z * (1.0f - 2.0f * sig));
}

// write value as bf16 hi/lo into A buffers; row-major, 528B row stride
__device__ __forceinline__ void storeA(char* sm, int row, int k, float v) {
    const uint32_t o = (uint32_t)row * ASTR + (uint32_t)k * 2;
    __nv_bfloat16 hi = __float2bfloat16(v);
    float rem = v - __bfloat162float(hi);
    __nv_bfloat16 lo = __float2bfloat16(rem);
    *reinterpret_cast<__nv_bfloat16*>(sm + OFF_AHI + o) = hi;
    *reinterpret_cast<__nv_bfloat16*>(sm + OFF_ALO + o) = lo;
}

// ---- prep: split W1..W3 into bf16 hi/lo ----
__global__ void prep_kernel(const float* __restrict__ W1, const float* __restrict__ W2,
                            const float* __restrict__ W3) {
    int i = blockIdx.x * blockDim.x + threadIdx.x;
    if (i >= 3 * 65536) return;
    const int layer = i >> 16;
    const int r = i & 65535;
    const float* W = (layer == 0) ? W1 : (layer == 1) ? W2 : W3;
    const float w = W[r];
    __nv_bfloat16 hi = __float2bfloat16(w);
    float rem = w - __bfloat162float(hi);
    g_Whi[i] = hi;
    g_Wlo[i] = __float2bfloat16(rem);
}

// ---- main kernel ----
__global__ __launch_bounds__(TPB, 1)
void pinn_mma_kernel(
    const float* __restrict__ x, const float* __restrict__ y,
    const float* __restrict__ t, const float* __restrict__ nu,
    const float* __restrict__ W0, const float* __restrict__ b0,
    const float* __restrict__ b1, const float* __restrict__ b2,
    const float* __restrict__ b3,
    const float* __restrict__ W4, const float* __restrict__ b4,
    float* __restrict__ out, int N)
{
    extern __shared__ char smem_raw[];
    const uint32_t rawa = smem_u32(smem_raw);
    const uint32_t sbase = (rawa + 1023u) & ~1023u;
    char* sm = smem_raw + (sbase - rawa);
    float* scr = reinterpret_cast<float*>(sm + OFF_SCR);   // [96][260], aliases B stage

    const int tid  = threadIdx.x;
    const int wid  = tid >> 5;       // 0..15
    const int lane = tid & 31;
    const int base = blockIdx.x * NPTS;

    const int mg = wid >> 3;          // 0..1 : M group (rows mg*48 .. +47)
    const int n0 = (wid & 7) * 32;    // N group start (32 cols per warp)

    const int nn  = tid & 255;        // neuron for layer0/epilogue
    const int ph  = tid >> 8;         // point-half: 0 -> pts 0..7, 1 -> pts 8..15

    // ---------------- layer 0: (4 -> 256) scalar -> A hi/lo -----------------
    {
        const float w0 = W0[nn], w1 = W0[256 + nn], w2 = W0[512 + nn], w3 = W0[768 + nn];
        const float bb = b0[nn];
        #pragma unroll 1
        for (int pp = 0; pp < 8; pp++) {
            const int p = ph * 8 + pp;
            int idx = base + p; if (idx >= N) idx = N - 1;
            const float xs = x[idx];
            const float ys = y[idx];
            const float ts = 2.0f * t[idx] - 1.0f;
            const float ns = 2.0f * (nu[idx] - 0.01f) * (1.0f / 0.09f) - 1.0f;
            const float z  = fmaf(xs, w0, fmaf(ys, w1, fmaf(ts, w2, fmaf(ns, w3, bb))));
            const float zx = w0, zy = w1, zt = 2.0f * w2;
            float s, sp, spp; swish_derivs(z, s, sp, spp);
            const int rb = p * 6;
            storeA(sm, rb + 0, nn, s);
            storeA(sm, rb + 1, nn, sp * zx);
            storeA(sm, rb + 2, nn, sp * zy);
            storeA(sm, rb + 3, nn, sp * zt);
            storeA(sm, rb + 4, nn, spp * zx * zx);
            storeA(sm, rb + 5, nn, spp * zy * zy);
        }
    }

    // ---------------- 3 hidden layers: bf16-split GEMM + swish --------------
    #pragma unroll 1
    for (int L = 0; L < 3; L++) {
        const float* __restrict__ bptr = (L == 0) ? b1 : (L == 1) ? b2 : b3;

        float acc[3][4][4];   // [m-tile][n-tile(8 cols)][frag]
        #pragma unroll
        for (int m = 0; m < 3; m++)
            #pragma unroll
            for (int nt = 0; nt < 4; nt++)
                #pragma unroll
                for (int r = 0; r < 4; r++) acc[m][nt][r] = 0.0f;

        #pragma unroll 1
        for (int kc = 0; kc < 4; kc++) {
            // stage W chunk (hi,lo): [64 k][256 n] bf16 -> smem rows of 528B
            __syncthreads();  // prior scr/B users done before overwrite
            #pragma unroll 1
            for (int i = tid; i < 4096; i += TPB) {
                const int split = i >> 11;
                const int r = (i >> 5) & 63;
                const int c = i & 31;
                const char* g = split ? (const char*)g_Wlo : (const char*)g_Whi;
                const uint4 v = *reinterpret_cast<const uint4*>(
                    g + (size_t)L * 131072 + (size_t)((kc * 64 + r) * 256 + c * 8) * 2);
                *reinterpret_cast<uint4*>(sm + OFF_B + split * BSPL + r * BSTR + c * 16) = v;
            }
            __syncthreads();

            #pragma unroll 1
            for (int split = 0; split < 3; split++) {
                // products: Ahi*Whi, Alo*Whi, Ahi*Wlo
                const uint32_t abase = sbase + ((split == 1) ? OFF_ALO : OFF_AHI);
                const uint32_t bbase = sbase + OFF_B + ((split == 2) ? BSPL : 0);
                #pragma unroll
                for (int ks = 0; ks < 4; ks++) {
                    uint32_t B[8];
                    #pragma unroll
                    for (int q = 0; q < 2; q++) {
                        const uint32_t addr = bbase
                            + (uint32_t)(ks * 16 + (lane & 15)) * BSTR
                            + (uint32_t)(n0 + q * 16 + (lane >> 4) * 8) * 2;
                        LDSM4T(B[q * 4], B[q * 4 + 1], B[q * 4 + 2], B[q * 4 + 3], addr);
                    }
                    #pragma unroll
                    for (int m = 0; m < 3; m++) {
                        uint32_t a0, a1, a2, a3;
                        const uint32_t addr = abase
                            + (uint32_t)(mg * 48 + m * 16 + (lane & 15)) * ASTR
                            + (uint32_t)(kc * 64 + ks * 16 + (lane >> 4) * 8) * 2;
                        LDSM4(a0, a1, a2, a3, addr);
                        #pragma unroll
                        for (int nt = 0; nt < 4; nt++) {
                            MMA_BF16(acc[m][nt], a0, a1, a2, a3,
                                     B[(nt >> 1) * 4 + (nt & 1) * 2],
                                     B[(nt >> 1) * 4 + (nt & 1) * 2 + 1]);
                        }
                    }
                }
            }
        }
        __syncthreads();   // B stage reads done; scr (aliased) may now be written

        // ---- epilogue: accums -> scratch -> swish chain -> A hi/lo ----
        #pragma unroll
        for (int m = 0; m < 3; m++) {
            const int row = mg * 48 + m * 16 + (lane >> 2);
            #pragma unroll
            for (int nt = 0; nt < 4; nt++) {
                const int col = n0 + nt * 8 + (lane & 3) * 2;
                float* p0 = scr + row * SCRSTR + col;
                p0[0] = acc[m][nt][0];
                p0[1] = acc[m][nt][1];
                float* p1 = p0 + 8 * SCRSTR;
                p1[0] = acc[m][nt][2];
                p1[1] = acc[m][nt][3];
            }
        }
        __syncthreads();

        {
            const float bn = bptr[nn];
            #pragma unroll 1
            for (int pp = 0; pp < 8; pp++) {
                const int p = ph * 8 + pp;
                const float* zr = scr + (p * 6) * SCRSTR + nn;
                const float z   = zr[0] + bn;
                const float zx  = zr[1 * SCRSTR];
                const float zy  = zr[2 * SCRSTR];
                const float zt  = zr[3 * SCRSTR];
                const float zxx = zr[4 * SCRSTR];
                const float zyy = zr[5 * SCRSTR];
                float s, sp, spp; swish_derivs(z, s, sp, spp);
                const int rb = p * 6;
                storeA(sm, rb + 0, nn, s);
                storeA(sm, rb + 1, nn, sp * zx);
                storeA(sm, rb + 2, nn, sp * zy);
                storeA(sm, rb + 3, nn, sp * zt);
                storeA(sm, rb + 4, nn, fmaf(spp, zx * zx, sp * zxx));
                storeA(sm, rb + 5, nn, fmaf(spp, zy * zy, sp * zyy));
            }
        }
        __syncthreads();
    }

    // ---------------- final layer (256 -> 2) + residual ---------------------
    if (tid < MROWS) {
        const int row = tid;
        float au = 0.0f, av = 0.0f;
        #pragma unroll 1
        for (int i = 0; i < 32; i++) {
            const int k0 = i * 8;
            const uint32_t o = (uint32_t)row * ASTR + (uint32_t)k0 * 2;
            const uint4 vh = *reinterpret_cast<const uint4*>(sm + OFF_AHI + o);
            const uint4 vl = *reinterpret_cast<const uint4*>(sm + OFF_ALO + o);
            const __nv_bfloat16* ph2 = reinterpret_cast<const __nv_bfloat16*>(&vh);
            const __nv_bfloat16* pl2 = reinterpret_cast<const __nv_bfloat16*>(&vl);
            #pragma unroll
            for (int e = 0; e < 8; e++) {
                const float v = __bfloat162float(ph2[e]) + __bfloat162float(pl2[e]);
                const float2 w = *reinterpret_cast<const float2*>(&W4[2 * (k0 + e)]);
                au = fmaf(v, w.x, au);
                av = fmaf(v, w.y, av);
            }
        }
        scr[row * 2 + 0] = au;
        scr[row * 2 + 1] = av;
    }
    __syncthreads();

    if (tid < NPTS) {
        const int idx = base + tid;
        if (idx < N) {
            const int rb = tid * 6;
            const float u   = scr[(rb + 0) * 2 + 0] + b4[0];
            const float v   = scr[(rb + 0) * 2 + 1] + b4[1];
            const float u_x = scr[(rb + 1) * 2 + 0], v_x = scr[(rb + 1) * 2 + 1];
            const float u_y = scr[(rb + 2) * 2 + 0], v_y = scr[(rb + 2) * 2 + 1];
            const float u_t = scr[(rb + 3) * 2 + 0], v_t = scr[(rb + 3) * 2 + 1];
            const float uxx = scr[(rb + 4) * 2 + 0], vxx = scr[(rb + 4) * 2 + 1];
            const float uyy = scr[(rb + 5) * 2 + 0], vyy = scr[(rb + 5) * 2 + 1];
            const float nv = nu[idx];
            out[idx * 2 + 0] = u_t + u * u_x + v * u_y - nv * (uxx + uyy);
            out[idx * 2 + 1] = v_t + u * v_x + v * v_y - nv * (vxx + vyy);
        }
    }
}

extern "C" void kernel_launch(void* const* d_in, const int* in_sizes, int n_in,
                              void* d_out, int out_size) {
    const float* x  = (const float*)d_in[0];
    const float* y  = (const float*)d_in[1];
    const float* t  = (const float*)d_in[2];
    const float* nu = (const float*)d_in[3];
    const float* W0 = (const float*)d_in[4];
    const float* b0 = (const float*)d_in[5];
    const float* W1 = (const float*)d_in[6];
    const float* b1 = (const float*)d_in[7];
    const float* W2 = (const float*)d_in[8];
    const float* b2 = (const float*)d_in[9];
    const float* W3 = (const float*)d_in[10];
    const float* b3 = (const float*)d_in[11];
    const float* W4 = (const float*)d_in[12];
    const float* b4 = (const float*)d_in[13];
    float* out = (float*)d_out;

    const int N = in_sizes[0];

    cudaFuncSetAttribute(pinn_mma_kernel, cudaFuncAttributeMaxDynamicSharedMemorySize, SMEM_BYTES);

    prep_kernel<<<(3 * 65536 + 255) / 256, 256>>>(W1, W2, W3);

    const int blocks = (N + NPTS - 1) / NPTS;
    pinn_mma_kernel<<<blocks, TPB, SMEM_BYTES>>>(x, y, t, nu, W0, b0,
                                                 b1, b2, b3, W4, b4, out, N);
}

// round 9
// speedup vs baseline: 2.1447x; 1.3090x over previous
#include <cuda_runtime.h>
#include <cuda_bf16.h>
#include <cstdint>

#define NPTS 16           // points per CTA
#define MROWS 96          // 16 points x 6 channels
#define TPB 512           // 16 warps

// ---- SMEM layout (byte offsets from 1024-aligned base) ----
#define ASTR    528       // A row stride bytes (264 halves; 256 used + pad)
#define OFF_AHI 0         // 96*528 = 50688
#define OFF_ALO 50688     // ends 101376
#define OFF_B   101376    // 3 x chunk buffers of 33792 B (2 splits x 32 k-rows x 528 B)
#define BUF_BYTES 33792
#define BSPL    16896     // split offset inside a chunk buffer (32*528)
#define BSTR    528
#define OFF_SCR 101376    // fp32 scratch [96][260] = 99840 — ALIASES buffers (temporally disjoint)
#define SCRSTR  260
#define SMEM_BYTES (101376 + 3 * 33792 + 1024)

// pre-split weights (hi/lo bf16), [3 layers][256 k][256 n]
__device__ __align__(16) __nv_bfloat16 g_Whi[3 * 256 * 256];
__device__ __align__(16) __nv_bfloat16 g_Wlo[3 * 256 * 256];

#define LDSM4(R0,R1,R2,R3,ADDR) \
  asm volatile("ldmatrix.sync.aligned.m8n8.x4.shared.b16 {%0,%1,%2,%3}, [%4];" \
    : "=r"(R0),"=r"(R1),"=r"(R2),"=r"(R3) : "r"(ADDR))
#define LDSM4T(R0,R1,R2,R3,ADDR) \
  asm volatile("ldmatrix.sync.aligned.m8n8.x4.trans.shared.b16 {%0,%1,%2,%3}, [%4];" \
    : "=r"(R0),"=r"(R1),"=r"(R2),"=r"(R3) : "r"(ADDR))
#define MMA_BF16(D,A0,A1,A2,A3,B0,B1) \
  asm volatile("mma.sync.aligned.m16n8k16.row.col.f32.bf16.bf16.f32 " \
    "{%0,%1,%2,%3},{%4,%5,%6,%7},{%8,%9},{%0,%1,%2,%3};" \
    : "+f"(D[0]),"+f"(D[1]),"+f"(D[2]),"+f"(D[3]) \
    : "r"(A0),"r"(A1),"r"(A2),"r"(A3),"r"(B0),"r"(B1))
#define CP16(S,G) asm volatile("cp.async.cg.shared.global [%0], [%1], 16;" :: "r"(S), "l"(G))
#define CP_COMMIT() asm volatile("cp.async.commit_group;" ::: "memory")
#define CP_WAIT1() asm volatile("cp.async.wait_group 1;" ::: "memory")
#define CP_WAIT0() asm volatile("cp.async.wait_group 0;" ::: "memory")

__device__ __forceinline__ uint32_t smem_u32(const void* p) {
    uint32_t a;
    asm("{ .reg .u64 t; cvta.to.shared.u64 t, %1; cvt.u32.u64 %0, t; }" : "=r"(a) : "l"(p));
    return a;
}

__device__ __forceinline__ void swish_derivs(float z, float& s, float& sp, float& spp) {
    float sig = 1.0f / (1.0f + __expf(-z));
    float om  = 1.0f - sig;
    s   = z * sig;
    sp  = sig * (1.0f + z * om);
    spp = sig * om * (2.0f + z * (1.0f - 2.0f * sig));
}

// write value as bf16 hi/lo into A buffers; row-major, 528B row stride
__device__ __forceinline__ void storeA(char* sm, int row, int k, float v) {
    const uint32_t o = (uint32_t)row * ASTR + (uint32_t)k * 2;
    __nv_bfloat16 hi = __float2bfloat16(v);
    float rem = v - __bfloat162float(hi);
    __nv_bfloat16 lo = __float2bfloat16(rem);
    *reinterpret_cast<__nv_bfloat16*>(sm + OFF_AHI + o) = hi;
    *reinterpret_cast<__nv_bfloat16*>(sm + OFF_ALO + o) = lo;
}

// ---- prep: split W1..W3 into bf16 hi/lo ----
__global__ void prep_kernel(const float* __restrict__ W1, const float* __restrict__ W2,
                            const float* __restrict__ W3) {
    int i = blockIdx.x * blockDim.x + threadIdx.x;
    if (i >= 3 * 65536) return;
    const int layer = i >> 16;
    const int r = i & 65535;
    const float* W = (layer == 0) ? W1 : (layer == 1) ? W2 : W3;
    const float w = W[r];
    __nv_bfloat16 hi = __float2bfloat16(w);
    float rem = w - __bfloat162float(hi);
    g_Whi[i] = hi;
    g_Wlo[i] = __float2bfloat16(rem);
}

// prefetch chunk c (32 k-rows, both splits) of layer L into buffer b via cp.async
__device__ __forceinline__ void prefetch_chunk(uint32_t sbase, int tid, int L, int c, int b) {
    // 2048 uint4: [split(2)][row(32)][32 x 16B]; each thread does 4
    const uint32_t dbase = sbase + OFF_B + (uint32_t)b * BUF_BYTES;
    #pragma unroll
    for (int it = 0; it < 4; it++) {
        const int i = tid + it * TPB;
        const int split = i >> 10;
        const int rem = i & 1023;
        const int r = rem >> 5;
        const int cc = rem & 31;
        const char* g = split ? (const char*)g_Wlo : (const char*)g_Whi;
        const char* src = g + (size_t)L * 131072 + (size_t)(c * 32 + r) * 512 + (size_t)cc * 16;
        const uint32_t dst = dbase + (uint32_t)split * BSPL + (uint32_t)r * BSTR + (uint32_t)cc * 16;
        CP16(dst, src);
    }
}

// ---- main kernel ----
__global__ __launch_bounds__(TPB, 1)
void pinn_mma_kernel(
    const float* __restrict__ x, const float* __restrict__ y,
    const float* __restrict__ t, const float* __restrict__ nu,
    const float* __restrict__ W0, const float* __restrict__ b0,
    const float* __restrict__ b1, const float* __restrict__ b2,
    const float* __restrict__ b3,
    const float* __restrict__ W4, const float* __restrict__ b4,
    float* __restrict__ out, int N)
{
    extern __shared__ char smem_raw[];
    const uint32_t rawa = smem_u32(smem_raw);
    const uint32_t sbase = (rawa + 1023u) & ~1023u;
    char* sm = smem_raw + (sbase - rawa);
    float* scr = reinterpret_cast<float*>(sm + OFF_SCR);   // [96][260], aliases buffers

    const int tid  = threadIdx.x;
    const int wid  = tid >> 5;       // 0..15
    const int lane = tid & 31;
    const int base = blockIdx.x * NPTS;

    const int mg = wid >> 3;          // 0..1 : M group (rows mg*48 .. +47)
    const int n0 = (wid & 7) * 32;    // N group start (32 cols per warp)

    const int nn  = tid & 255;        // neuron for layer0/epilogue
    const int ph  = tid >> 8;         // point-half: 0 -> pts 0..7, 1 -> pts 8..15

    // ---------------- layer 0: (4 -> 256) scalar -> A hi/lo -----------------
    {
        const float w0 = W0[nn], w1 = W0[256 + nn], w2 = W0[512 + nn], w3 = W0[768 + nn];
        const float bb = b0[nn];
        #pragma unroll 1
        for (int pp = 0; pp < 8; pp++) {
            const int p = ph * 8 + pp;
            int idx = base + p; if (idx >= N) idx = N - 1;
            const float xs = x[idx];
            const float ys = y[idx];
            const float ts = 2.0f * t[idx] - 1.0f;
            const float ns = 2.0f * (nu[idx] - 0.01f) * (1.0f / 0.09f) - 1.0f;
            const float z  = fmaf(xs, w0, fmaf(ys, w1, fmaf(ts, w2, fmaf(ns, w3, bb))));
            const float zx = w0, zy = w1, zt = 2.0f * w2;
            float s, sp, spp; swish_derivs(z, s, sp, spp);
            const int rb = p * 6;
            storeA(sm, rb + 0, nn, s);
            storeA(sm, rb + 1, nn, sp * zx);
            storeA(sm, rb + 2, nn, sp * zy);
            storeA(sm, rb + 3, nn, sp * zt);
            storeA(sm, rb + 4, nn, spp * zx * zx);
            storeA(sm, rb + 5, nn, spp * zy * zy);
        }
    }
    __syncthreads();

    // ---------------- 3 hidden layers: bf16-split GEMM + swish --------------
    #pragma unroll 1
    for (int L = 0; L < 3; L++) {
        const float* __restrict__ bptr = (L == 0) ? b1 : (L == 1) ? b2 : b3;

        float acc[3][4][4];   // [m-tile][n-tile(8 cols)][frag]
        #pragma unroll
        for (int m = 0; m < 3; m++)
            #pragma unroll
            for (int nt = 0; nt < 4; nt++)
                #pragma unroll
                for (int r = 0; r < 4; r++) acc[m][nt][r] = 0.0f;

        prefetch_chunk(sbase, tid, L, 0, 0); CP_COMMIT();
        prefetch_chunk(sbase, tid, L, 1, 1); CP_COMMIT();

        #pragma unroll 1
        for (int c = 0; c < 8; c++) {
            if (c < 7) { CP_WAIT1(); } else { CP_WAIT0(); }
            __syncthreads();                       // chunk c visible to all; prior readers done
            if (c + 2 < 8) { prefetch_chunk(sbase, tid, L, c + 2, (c + 2) % 3); CP_COMMIT(); }

            const uint32_t bufb = sbase + OFF_B + (uint32_t)(c % 3) * BUF_BYTES;
            #pragma unroll
            for (int ks = 0; ks < 2; ks++) {
                // load B fragments once: hi and lo
                uint32_t Bh[8], Bl[8];
                #pragma unroll
                for (int q = 0; q < 2; q++) {
                    const uint32_t roff = (uint32_t)(ks * 16 + (lane & 15)) * BSTR
                                        + (uint32_t)(n0 + q * 16 + (lane >> 4) * 8) * 2;
                    LDSM4T(Bh[q * 4], Bh[q * 4 + 1], Bh[q * 4 + 2], Bh[q * 4 + 3], bufb + roff);
                    LDSM4T(Bl[q * 4], Bl[q * 4 + 1], Bl[q * 4 + 2], Bl[q * 4 + 3], bufb + BSPL + roff);
                }
                #pragma unroll
                for (int m = 0; m < 3; m++) {
                    const uint32_t aroff = (uint32_t)(mg * 48 + m * 16 + (lane & 15)) * ASTR
                                         + (uint32_t)(c * 32 + ks * 16 + (lane >> 4) * 8) * 2;
                    uint32_t ah0, ah1, ah2, ah3, al0, al1, al2, al3;
                    LDSM4(ah0, ah1, ah2, ah3, sbase + OFF_AHI + aroff);
                    LDSM4(al0, al1, al2, al3, sbase + OFF_ALO + aroff);
                    #pragma unroll
                    for (int nt = 0; nt < 4; nt++)
                        MMA_BF16(acc[m][nt], ah0, ah1, ah2, ah3, Bh[nt * 2], Bh[nt * 2 + 1]);
                    #pragma unroll
                    for (int nt = 0; nt < 4; nt++)
                        MMA_BF16(acc[m][nt], al0, al1, al2, al3, Bh[nt * 2], Bh[nt * 2 + 1]);
                    #pragma unroll
                    for (int nt = 0; nt < 4; nt++)
                        MMA_BF16(acc[m][nt], ah0, ah1, ah2, ah3, Bl[nt * 2], Bl[nt * 2 + 1]);
                }
            }
        }
        __syncthreads();   // all MMA buffer reads done; scr (aliased) may now be written

        // ---- epilogue: accums -> scratch -> swish chain -> A hi/lo ----
        #pragma unroll
        for (int m = 0; m < 3; m++) {
            const int row = mg * 48 + m * 16 + (lane >> 2);
            #pragma unroll
            for (int nt = 0; nt < 4; nt++) {
                const int col = n0 + nt * 8 + (lane & 3) * 2;
                float* p0 = scr + row * SCRSTR + col;
                p0[0] = acc[m][nt][0];
                p0[1] = acc[m][nt][1];
                float* p1 = p0 + 8 * SCRSTR;
                p1[0] = acc[m][nt][2];
                p1[1] = acc[m][nt][3];
            }
        }
        __syncthreads();

        {
            const float bn = bptr[nn];
            #pragma unroll 1
            for (int pp = 0; pp < 8; pp++) {
                const int p = ph * 8 + pp;
                const float* zr = scr + (p * 6) * SCRSTR + nn;
                const float z   = zr[0] + bn;
                const float zx  = zr[1 * SCRSTR];
                const float zy  = zr[2 * SCRSTR];
                const float zt  = zr[3 * SCRSTR];
                const float zxx = zr[4 * SCRSTR];
                const float zyy = zr[5 * SCRSTR];
                float s, sp, spp; swish_derivs(z, s, sp, spp);
                const int rb = p * 6;
                storeA(sm, rb + 0, nn, s);
                storeA(sm, rb + 1, nn, sp * zx);
                storeA(sm, rb + 2, nn, sp * zy);
                storeA(sm, rb + 3, nn, sp * zt);
                storeA(sm, rb + 4, nn, fmaf(spp, zx * zx, sp * zxx));
                storeA(sm, rb + 5, nn, fmaf(spp, zy * zy, sp * zyy));
            }
        }
        __syncthreads();
    }

    // ---------------- final layer (256 -> 2) + residual ---------------------
    if (tid < MROWS) {
        const int row = tid;
        float au = 0.0f, av = 0.0f;
        #pragma unroll 1
        for (int i = 0; i < 32; i++) {
            const int k0 = i * 8;
            const uint32_t o = (uint32_t)row * ASTR + (uint32_t)k0 * 2;
            const uint4 vh = *reinterpret_cast<const uint4*>(sm + OFF_AHI + o);
            const uint4 vl = *reinterpret_cast<const uint4*>(sm + OFF_ALO + o);
            const __nv_bfloat16* ph2 = reinterpret_cast<const __nv_bfloat16*>(&vh);
            const __nv_bfloat16* pl2 = reinterpret_cast<const __nv_bfloat16*>(&vl);
            #pragma unroll
            for (int e = 0; e < 8; e++) {
                const float v = __bfloat162float(ph2[e]) + __bfloat162float(pl2[e]);
                const float2 w = *reinterpret_cast<const float2*>(&W4[2 * (k0 + e)]);
                au = fmaf(v, w.x, au);
                av = fmaf(v, w.y, av);
            }
        }
        scr[row * 2 + 0] = au;
        scr[row * 2 + 1] = av;
    }
    __syncthreads();

    if (tid < NPTS) {
        const int idx = base + tid;
        if (idx < N) {
            const int rb = tid * 6;
            const float u   = scr[(rb + 0) * 2 + 0] + b4[0];
            const float v   = scr[(rb + 0) * 2 + 1] + b4[1];
            const float u_x = scr[(rb + 1) * 2 + 0], v_x = scr[(rb + 1) * 2 + 1];
            const float u_y = scr[(rb + 2) * 2 + 0], v_y = scr[(rb + 2) * 2 + 1];
            const float u_t = scr[(rb + 3) * 2 + 0], v_t = scr[(rb + 3) * 2 + 1];
            const float uxx = scr[(rb + 4) * 2 + 0], vxx = scr[(rb + 4) * 2 + 1];
            const float uyy = scr[(rb + 5) * 2 + 0], vyy = scr[(rb + 5) * 2 + 1];
            const float nv = nu[idx];
            out[idx * 2 + 0] = u_t + u * u_x + v * u_y - nv * (uxx + uyy);
            out[idx * 2 + 1] = v_t + u * v_x + v * v_y - nv * (vxx + vyy);
        }
    }
}

extern "C" void kernel_launch(void* const* d_in, const int* in_sizes, int n_in,
                              void* d_out, int out_size) {
    const float* x  = (const float*)d_in[0];
    const float* y  = (const float*)d_in[1];
    const float* t  = (const float*)d_in[2];
    const float* nu = (const float*)d_in[3];
    const float* W0 = (const float*)d_in[4];
    const float* b0 = (const float*)d_in[5];
    const float* W1 = (const float*)d_in[6];
    const float* b1 = (const float*)d_in[7];
    const float* W2 = (const float*)d_in[8];
    const float* b2 = (const float*)d_in[9];
    const float* W3 = (const float*)d_in[10];
    const float* b3 = (const float*)d_in[11];
    const float* W4 = (const float*)d_in[12];
    const float* b4 = (const float*)d_in[13];
    float* out = (float*)d_out;

    const int N = in_sizes[0];

    cudaFuncSetAttribute(pinn_mma_kernel, cudaFuncAttributeMaxDynamicSharedMemorySize, SMEM_BYTES);

    prep_kernel<<<(3 * 65536 + 255) / 256, 256>>>(W1, W2, W3);

    const int blocks = (N + NPTS - 1) / NPTS;
    pinn_mma_kernel<<<blocks, TPB, SMEM_BYTES>>>(x, y, t, nu, W0, b0,
                                                 b1, b2, b3, W4, b4, out, N);
}

// round 10
// speedup vs baseline: 2.1919x; 1.0220x over previous
#include <cuda_runtime.h>
#include <cuda_bf16.h>
#include <cstdint>

#define NPTS 16           // points per CTA
#define MROWS 96          // 16 points x 6 channels
#define TPB 512           // 16 warps

// ---- SMEM layout (byte offsets from 1024-aligned base) ----
#define ASTR    528       // A row stride bytes (264 halves; 256 used + pad)
#define OFF_AHI 0         // 96*528 = 50688
#define OFF_ALO 50688     // ends 101376
#define OFF_B   101376    // 3 x chunk buffers of 33792 B (2 splits x 32 k-rows x 528 B)
#define BUF_BYTES 33792
#define BSPL    16896     // split offset inside a chunk buffer (32*528)
#define BSTR    528
#define OFF_SCR 101376    // fp32 scratch [96][260] = 99840 — ALIASES buffers (temporally disjoint)
#define SCRSTR  260
#define SMEM_BYTES (101376 + 3 * 33792 + 1024)

// pre-split weights (hi/lo bf16), [3 layers][256 k][256 n]
__device__ __align__(16) __nv_bfloat16 g_Whi[3 * 256 * 256];
__device__ __align__(16) __nv_bfloat16 g_Wlo[3 * 256 * 256];

#define LDSM4(R0,R1,R2,R3,ADDR) \
  asm volatile("ldmatrix.sync.aligned.m8n8.x4.shared.b16 {%0,%1,%2,%3}, [%4];" \
    : "=r"(R0),"=r"(R1),"=r"(R2),"=r"(R3) : "r"(ADDR))
#define LDSM4T(R0,R1,R2,R3,ADDR) \
  asm volatile("ldmatrix.sync.aligned.m8n8.x4.trans.shared.b16 {%0,%1,%2,%3}, [%4];" \
    : "=r"(R0),"=r"(R1),"=r"(R2),"=r"(R3) : "r"(ADDR))
#define MMA_BF16(D,A0,A1,A2,A3,B0,B1) \
  asm volatile("mma.sync.aligned.m16n8k16.row.col.f32.bf16.bf16.f32 " \
    "{%0,%1,%2,%3},{%4,%5,%6,%7},{%8,%9},{%0,%1,%2,%3};" \
    : "+f"(D[0]),"+f"(D[1]),"+f"(D[2]),"+f"(D[3]) \
    : "r"(A0),"r"(A1),"r"(A2),"r"(A3),"r"(B0),"r"(B1))
#define CP16(S,G) asm volatile("cp.async.cg.shared.global [%0], [%1], 16;" :: "r"(S), "l"(G))
#define CP_COMMIT() asm volatile("cp.async.commit_group;" ::: "memory")
#define CP_WAIT1() asm volatile("cp.async.wait_group 1;" ::: "memory")
#define CP_WAIT0() asm volatile("cp.async.wait_group 0;" ::: "memory")

__device__ __forceinline__ uint32_t smem_u32(const void* p) {
    uint32_t a;
    asm("{ .reg .u64 t; cvta.to.shared.u64 t, %1; cvt.u32.u64 %0, t; }" : "=r"(a) : "l"(p));
    return a;
}

__device__ __forceinline__ void swish_derivs(float z, float& s, float& sp, float& spp) {
    float sig = 1.0f / (1.0f + __expf(-z));
    float om  = 1.0f - sig;
    s   = z * sig;
    sp  = sig * (1.0f + z * om);
    spp = sig * om * (2.0f + z * (1.0f - 2.0f * sig));
}

// write value as bf16 hi/lo into A buffers; row-major, 528B row stride
__device__ __forceinline__ void storeA(char* sm, int row, int k, float v) {
    const uint32_t o = (uint32_t)row * ASTR + (uint32_t)k * 2;
    __nv_bfloat16 hi = __float2bfloat16(v);
    float rem = v - __bfloat162float(hi);
    __nv_bfloat16 lo = __float2bfloat16(rem);
    *reinterpret_cast<__nv_bfloat16*>(sm + OFF_AHI + o) = hi;
    *reinterpret_cast<__nv_bfloat16*>(sm + OFF_ALO + o) = lo;
}

// ---- prep: split W1..W3 into bf16 hi/lo ----
__global__ void prep_kernel(const float* __restrict__ W1, const float* __restrict__ W2,
                            const float* __restrict__ W3) {
    int i = blockIdx.x * blockDim.x + threadIdx.x;
    if (i >= 3 * 65536) return;
    const int layer = i >> 16;
    const int r = i & 65535;
    const float* W = (layer == 0) ? W1 : (layer == 1) ? W2 : W3;
    const float w = W[r];
    __nv_bfloat16 hi = __float2bfloat16(w);
    float rem = w - __bfloat162float(hi);
    g_Whi[i] = hi;
    g_Wlo[i] = __float2bfloat16(rem);
}

// prefetch chunk c (32 k-rows, both splits) of layer L into buffer b via cp.async
__device__ __forceinline__ void prefetch_chunk(uint32_t sbase, int tid, int L, int c, int b) {
    const uint32_t dbase = sbase + OFF_B + (uint32_t)b * BUF_BYTES;
    #pragma unroll
    for (int it = 0; it < 4; it++) {
        const int i = tid + it * TPB;
        const int split = i >> 10;
        const int rem = i & 1023;
        const int r = rem >> 5;
        const int cc = rem & 31;
        const char* g = split ? (const char*)g_Wlo : (const char*)g_Whi;
        const char* src = g + (size_t)L * 131072 + (size_t)(c * 32 + r) * 512 + (size_t)cc * 16;
        const uint32_t dst = dbase + (uint32_t)split * BSPL + (uint32_t)r * BSTR + (uint32_t)cc * 16;
        CP16(dst, src);
    }
}

// ---- main kernel ----
__global__ __launch_bounds__(TPB, 1)
void pinn_mma_kernel(
    const float* __restrict__ x, const float* __restrict__ y,
    const float* __restrict__ t, const float* __restrict__ nu,
    const float* __restrict__ W0, const float* __restrict__ b0,
    const float* __restrict__ b1, const float* __restrict__ b2,
    const float* __restrict__ b3,
    const float* __restrict__ W4, const float* __restrict__ b4,
    float* __restrict__ out, int N)
{
    extern __shared__ char smem_raw[];
    const uint32_t rawa = smem_u32(smem_raw);
    const uint32_t sbase = (rawa + 1023u) & ~1023u;
    char* sm = smem_raw + (sbase - rawa);
    float* scr = reinterpret_cast<float*>(sm + OFF_SCR);   // [96][260], aliases buffers

    const int tid  = threadIdx.x;
    const int wid  = tid >> 5;       // 0..15
    const int lane = tid & 31;
    const int base = blockIdx.x * NPTS;

    const int mg = wid >> 3;          // 0..1 : M group (rows mg*48 .. +47)
    const int n0 = (wid & 7) * 32;    // N group start (32 cols per warp)

    const int nn  = tid & 255;        // neuron for layer0/epilogue
    const int ph  = tid >> 8;         // point-half: 0 -> pts 0..7, 1 -> pts 8..15

    // prefetch layer-0 weight chunks behind the scalar layer-0 phase
    prefetch_chunk(sbase, tid, 0, 0, 0); CP_COMMIT();
    prefetch_chunk(sbase, tid, 0, 1, 1); CP_COMMIT();

    // ---------------- layer 0: (4 -> 256) scalar -> A hi/lo -----------------
    {
        const float w0 = W0[nn], w1 = W0[256 + nn], w2 = W0[512 + nn], w3 = W0[768 + nn];
        const float bb = b0[nn];
        #pragma unroll 1
        for (int pp = 0; pp < 8; pp++) {
            const int p = ph * 8 + pp;
            int idx = base + p; if (idx >= N) idx = N - 1;
            const float xs = x[idx];
            const float ys = y[idx];
            const float ts = 2.0f * t[idx] - 1.0f;
            const float ns = 2.0f * (nu[idx] - 0.01f) * (1.0f / 0.09f) - 1.0f;
            const float z  = fmaf(xs, w0, fmaf(ys, w1, fmaf(ts, w2, fmaf(ns, w3, bb))));
            const float zx = w0, zy = w1, zt = 2.0f * w2;
            float s, sp, spp; swish_derivs(z, s, sp, spp);
            const int rb = p * 6;
            storeA(sm, rb + 0, nn, s);
            storeA(sm, rb + 1, nn, sp * zx);
            storeA(sm, rb + 2, nn, sp * zy);
            storeA(sm, rb + 3, nn, sp * zt);
            storeA(sm, rb + 4, nn, spp * zx * zx);
            storeA(sm, rb + 5, nn, spp * zy * zy);
        }
    }
    __syncthreads();

    // ---------------- 3 hidden layers: bf16-split GEMM + swish --------------
    #pragma unroll 1
    for (int L = 0; L < 3; L++) {
        const float* __restrict__ bptr = (L == 0) ? b1 : (L == 1) ? b2 : b3;

        float acc[3][4][4];   // [m-tile][n-tile(8 cols)][frag]
        #pragma unroll
        for (int m = 0; m < 3; m++)
            #pragma unroll
            for (int nt = 0; nt < 4; nt++)
                #pragma unroll
                for (int r = 0; r < 4; r++) acc[m][nt][r] = 0.0f;

        if (L > 0) {
            prefetch_chunk(sbase, tid, L, 0, 0); CP_COMMIT();
            prefetch_chunk(sbase, tid, L, 1, 1); CP_COMMIT();
        }

        #pragma unroll 1
        for (int c = 0; c < 8; c++) {
            if (c < 7) { CP_WAIT1(); } else { CP_WAIT0(); }
            __syncthreads();                       // chunk c visible to all; prior readers done
            if (c + 2 < 8) { prefetch_chunk(sbase, tid, L, c + 2, (c + 2) % 3); CP_COMMIT(); }

            const uint32_t bufb = sbase + OFF_B + (uint32_t)(c % 3) * BUF_BYTES;
            #pragma unroll
            for (int ks = 0; ks < 2; ks++) {
                // load B fragments once: hi and lo
                uint32_t Bh[8], Bl[8];
                #pragma unroll
                for (int q = 0; q < 2; q++) {
                    const uint32_t roff = (uint32_t)(ks * 16 + (lane & 15)) * BSTR
                                        + (uint32_t)(n0 + q * 16 + (lane >> 4) * 8) * 2;
                    LDSM4T(Bh[q * 4], Bh[q * 4 + 1], Bh[q * 4 + 2], Bh[q * 4 + 3], bufb + roff);
                    LDSM4T(Bl[q * 4], Bl[q * 4 + 1], Bl[q * 4 + 2], Bl[q * 4 + 3], bufb + BSPL + roff);
                }
                // load ALL m-tiles' Ahi fragments up front
                uint32_t Ah[3][4];
                uint32_t aroff[3];
                #pragma unroll
                for (int m = 0; m < 3; m++) {
                    aroff[m] = (uint32_t)(mg * 48 + m * 16 + (lane & 15)) * ASTR
                             + (uint32_t)(c * 32 + ks * 16 + (lane >> 4) * 8) * 2;
                    LDSM4(Ah[m][0], Ah[m][1], Ah[m][2], Ah[m][3], sbase + OFF_AHI + aroff[m]);
                }
                // set 1: Ahi x Bhi  (12 independent MMAs)
                #pragma unroll
                for (int m = 0; m < 3; m++)
                    #pragma unroll
                    for (int nt = 0; nt < 4; nt++)
                        MMA_BF16(acc[m][nt], Ah[m][0], Ah[m][1], Ah[m][2], Ah[m][3],
                                 Bh[nt * 2], Bh[nt * 2 + 1]);
                // set 2: Ahi x Blo  (12 independent MMAs; covers Alo LDSM latency)
                #pragma unroll
                for (int m = 0; m < 3; m++)
                    #pragma unroll
                    for (int nt = 0; nt < 4; nt++)
                        MMA_BF16(acc[m][nt], Ah[m][0], Ah[m][1], Ah[m][2], Ah[m][3],
                                 Bl[nt * 2], Bl[nt * 2 + 1]);
                // load Alo, set 3: Alo x Bhi
                uint32_t Al[3][4];
                #pragma unroll
                for (int m = 0; m < 3; m++)
                    LDSM4(Al[m][0], Al[m][1], Al[m][2], Al[m][3], sbase + OFF_ALO + aroff[m]);
                #pragma unroll
                for (int m = 0; m < 3; m++)
                    #pragma unroll
                    for (int nt = 0; nt < 4; nt++)
                        MMA_BF16(acc[m][nt], Al[m][0], Al[m][1], Al[m][2], Al[m][3],
                                 Bh[nt * 2], Bh[nt * 2 + 1]);
            }
        }
        __syncthreads();   // all MMA buffer reads done; scr (aliased) may now be written

        // ---- epilogue: accums -> scratch -> swish chain -> A hi/lo ----
        #pragma unroll
        for (int m = 0; m < 3; m++) {
            const int row = mg * 48 + m * 16 + (lane >> 2);
            #pragma unroll
            for (int nt = 0; nt < 4; nt++) {
                const int col = n0 + nt * 8 + (lane & 3) * 2;
                float* p0 = scr + row * SCRSTR + col;
                p0[0] = acc[m][nt][0];
                p0[1] = acc[m][nt][1];
                float* p1 = p0 + 8 * SCRSTR;
                p1[0] = acc[m][nt][2];
                p1[1] = acc[m][nt][3];
            }
        }
        __syncthreads();

        {
            const float bn = bptr[nn];
            #pragma unroll 1
            for (int pp = 0; pp < 8; pp++) {
                const int p = ph * 8 + pp;
                const float* zr = scr + (p * 6) * SCRSTR + nn;
                const float z   = zr[0] + bn;
                const float zx  = zr[1 * SCRSTR];
                const float zy  = zr[2 * SCRSTR];
                const float zt  = zr[3 * SCRSTR];
                const float zxx = zr[4 * SCRSTR];
                const float zyy = zr[5 * SCRSTR];
                float s, sp, spp; swish_derivs(z, s, sp, spp);
                const int rb = p * 6;
                storeA(sm, rb + 0, nn, s);
                storeA(sm, rb + 1, nn, sp * zx);
                storeA(sm, rb + 2, nn, sp * zy);
                storeA(sm, rb + 3, nn, sp * zt);
                storeA(sm, rb + 4, nn, fmaf(spp, zx * zx, sp * zxx));
                storeA(sm, rb + 5, nn, fmaf(spp, zy * zy, sp * zyy));
            }
        }
        __syncthreads();
    }

    // ---------------- final layer (256 -> 2) + residual ---------------------
    if (tid < MROWS) {
        const int row = tid;
        float au = 0.0f, av = 0.0f;
        #pragma unroll 1
        for (int i = 0; i < 32; i++) {
            const int k0 = i * 8;
            const uint32_t o = (uint32_t)row * ASTR + (uint32_t)k0 * 2;
            const uint4 vh = *reinterpret_cast<const uint4*>(sm + OFF_AHI + o);
            const uint4 vl = *reinterpret_cast<const uint4*>(sm + OFF_ALO + o);
            const __nv_bfloat16* ph2 = reinterpret_cast<const __nv_bfloat16*>(&vh);
            const __nv_bfloat16* pl2 = reinterpret_cast<const __nv_bfloat16*>(&vl);
            #pragma unroll
            for (int e = 0; e < 8; e++) {
                const float v = __bfloat162float(ph2[e]) + __bfloat162float(pl2[e]);
                const float2 w = *reinterpret_cast<const float2*>(&W4[2 * (k0 + e)]);
                au = fmaf(v, w.x, au);
                av = fmaf(v, w.y, av);
            }
        }
        scr[row * 2 + 0] = au;
        scr[row * 2 + 1] = av;
    }
    __syncthreads();

    if (tid < NPTS) {
        const int idx = base + tid;
        if (idx < N) {
            const int rb = tid * 6;
            const float u   = scr[(rb + 0) * 2 + 0] + b4[0];
            const float v   = scr[(rb + 0) * 2 + 1] + b4[1];
            const float u_x = scr[(rb + 1) * 2 + 0], v_x = scr[(rb + 1) * 2 + 1];
            const float u_y = scr[(rb + 2) * 2 + 0], v_y = scr[(rb + 2) * 2 + 1];
            const float u_t = scr[(rb + 3) * 2 + 0], v_t = scr[(rb + 3) * 2 + 1];
            const float uxx = scr[(rb + 4) * 2 + 0], vxx = scr[(rb + 4) * 2 + 1];
            const float uyy = scr[(rb + 5) * 2 + 0], vyy = scr[(rb + 5) * 2 + 1];
            const float nv = nu[idx];
            out[idx * 2 + 0] = u_t + u * u_x + v * u_y - nv * (uxx + uyy);
            out[idx * 2 + 1] = v_t + u * v_x + v * v_y - nv * (vxx + vyy);
        }
    }
}

extern "C" void kernel_launch(void* const* d_in, const int* in_sizes, int n_in,
                              void* d_out, int out_size) {
    const float* x  = (const float*)d_in[0];
    const float* y  = (const float*)d_in[1];
    const float* t  = (const float*)d_in[2];
    const float* nu = (const float*)d_in[3];
    const float* W0 = (const float*)d_in[4];
    const float* b0 = (const float*)d_in[5];
    const float* W1 = (const float*)d_in[6];
    const float* b1 = (const float*)d_in[7];
    const float* W2 = (const float*)d_in[8];
    const float* b2 = (const float*)d_in[9];
    const float* W3 = (const float*)d_in[10];
    const float* b3 = (const float*)d_in[11];
    const float* W4 = (const float*)d_in[12];
    const float* b4 = (const float*)d_in[13];
    float* out = (float*)d_out;

    const int N = in_sizes[0];

    cudaFuncSetAttribute(pinn_mma_kernel, cudaFuncAttributeMaxDynamicSharedMemorySize, SMEM_BYTES);

    prep_kernel<<<(3 * 65536 + 255) / 256, 256>>>(W1, W2, W3);

    const int blocks = (N + NPTS - 1) / NPTS;
    pinn_mma_kernel<<<blocks, TPB, SMEM_BYTES>>>(x, y, t, nu, W0, b0,
                                                 b1, b2, b3, W4, b4, out, N);
}